// round 12
// baseline (speedup 1.0000x reference)
#include <cuda_runtime.h>
#include <cuda_bf16.h>
#include <cuda_fp16.h>
#include <math.h>
#include <stdint.h>

// Problem constants
#define BB 32
#define TT 256
#define DD 2048
#define HH 16
#define DKK 64

__device__ float g_proj[8192 * 2048];   // k|v projections (B*T, 2048)
__device__ float g_bg[8192 * 32];       // beta logits (0..15), gamma logits (16..31)

// fp16 operand planes (single product: C = A_f16 * B_f16)
__device__ __half g_Af16[8192 * 2048];  // content (written by proj_bg)
__device__ __half g_Bf16[2048 * 2048];  // weights; rows 0..1023 = k_w, 1024.. = v_w

__device__ __forceinline__ uint32_t smem_u32(const void* p) {
    uint32_t a;
    asm("{ .reg .u64 t; cvta.to.shared.u64 t, %1; cvt.u32.u64 %0, t; }" : "=r"(a) : "l"(p));
    return a;
}

#define N4_W (1024 * 2048 / 4)

// ---------------------------------------------------------------------------
// Kernel 2 (runs first): beta/gamma logits + content->fp16 fused,
// + weights->fp16 conversion in the tail (replaces cvt_w kernel).
// ---------------------------------------------------------------------------
__global__ __launch_bounds__(256)
void proj_bg(const float* __restrict__ A,
             const float* __restrict__ b_w,
             const float* __restrict__ ts_w,
             const float* __restrict__ b_b,
             const float* __restrict__ ts_b,
             const float4* __restrict__ kw4,
             const float4* __restrict__ vw4)
{
    __shared__ float As[32][128];
    __shared__ float Ws[32][129];

    const int rb = blockIdx.x * 32;
    const int tid = threadIdx.x;
    const int r0 = (tid >> 4) * 2;
    const int j0 = (tid & 15) * 2;
    float a00 = 0.f, a01 = 0.f, a10 = 0.f, a11 = 0.f;

    for (int k0 = 0; k0 < DD; k0 += 128) {
        __syncthreads();
#pragma unroll
        for (int it = 0; it < 8; it++) {
            int idx = tid + it * 256;
            int row = idx >> 6, c2 = idx & 63;
            const float2 v = *reinterpret_cast<const float2*>(
                A + (size_t)(rb + row) * DD + k0 + c2 * 2);
            As[row][c2 * 2] = v.x;
            As[row][c2 * 2 + 1] = v.y;
            uint32_t hcv;
            asm("cvt.rn.f16x2.f32 %0, %2, %1;" : "=r"(hcv) : "f"(v.x), "f"(v.y));
            *reinterpret_cast<uint32_t*>(
                g_Af16 + (size_t)(rb + row) * DD + k0 + c2 * 2) = hcv;
        }
#pragma unroll
        for (int it = 0; it < 8; it++) {
            int idx = tid + it * 256;
            int wr = idx >> 6, wc2 = idx & 63;
            const float* wsrc = (wr < 16) ? (b_w + (size_t)wr * DD)
                                          : (ts_w + (size_t)(wr - 16) * DD);
            const float2 v = *reinterpret_cast<const float2*>(wsrc + k0 + wc2 * 2);
            Ws[wr][wc2 * 2] = v.x;
            Ws[wr][wc2 * 2 + 1] = v.y;
        }
        __syncthreads();
#pragma unroll 4
        for (int d = 0; d < 128; d++) {
            float x0 = As[r0][d], x1 = As[r0 + 1][d];
            float w0 = Ws[j0][d], w1 = Ws[j0 + 1][d];
            a00 = fmaf(x0, w0, a00);
            a01 = fmaf(x0, w1, a01);
            a10 = fmaf(x1, w0, a10);
            a11 = fmaf(x1, w1, a11);
        }
    }

    float bias0 = (j0 < 16) ? b_b[j0] : ts_b[j0 - 16];
    float bias1 = (j0 + 1 < 16) ? b_b[j0 + 1] : ts_b[j0 + 1 - 16];
    g_bg[(size_t)(rb + r0) * 32 + j0]         = a00 + bias0;
    g_bg[(size_t)(rb + r0) * 32 + j0 + 1]     = a01 + bias1;
    g_bg[(size_t)(rb + r0 + 1) * 32 + j0]     = a10 + bias0;
    g_bg[(size_t)(rb + r0 + 1) * 32 + j0 + 1] = a11 + bias1;

    // tail: convert weights to fp16 (grid-stride)
    for (int i = blockIdx.x * 256 + tid; i < 2 * N4_W; i += 256 * 256) {
        const float4* src = (i < N4_W) ? kw4 : vw4;
        uint2* dst = (i < N4_W) ? (uint2*)g_Bf16 : (uint2*)(g_Bf16 + 1024 * 2048);
        int j = (i < N4_W) ? i : i - N4_W;
        float4 x = src[j];
        uint2 hv;
        asm("cvt.rn.f16x2.f32 %0, %2, %1;" : "=r"(hv.x) : "f"(x.x), "f"(x.y));
        asm("cvt.rn.f16x2.f32 %0, %2, %1;" : "=r"(hv.y) : "f"(x.z), "f"(x.w));
        dst[j] = hv;
    }
}

// ---------------------------------------------------------------------------
// Kernel 1: GEMM, single-product fp16.
// CTA 128x128, K-chunk 16, 4-stage cp.async pipeline, warp layout 2x4.
// ---------------------------------------------------------------------------
#define TM 128
#define TN 128
#define TK 16
#define NCH (DD / TK)        // 128
#define PITCH 48
#define PLANE (128 * PITCH)  // 6144
#define STAGE (2 * PLANE)    // 12288
#define NSTG 4
#define SMEMG (NSTG * STAGE) // 49152

__device__ __forceinline__ void ldmx4(uint32_t* r, uint32_t addr) {
    asm volatile("ldmatrix.sync.aligned.m8n8.x4.shared.b16 {%0,%1,%2,%3}, [%4];"
                 : "=r"(r[0]), "=r"(r[1]), "=r"(r[2]), "=r"(r[3]) : "r"(addr));
}
__device__ __forceinline__ void mma16816(float* d, const uint32_t* a,
                                         uint32_t b0, uint32_t b1) {
    asm volatile(
        "mma.sync.aligned.m16n8k16.row.col.f32.f16.f16.f32 "
        "{%0,%1,%2,%3}, {%4,%5,%6,%7}, {%8,%9}, {%0,%1,%2,%3};"
        : "+f"(d[0]), "+f"(d[1]), "+f"(d[2]), "+f"(d[3])
        : "r"(a[0]), "r"(a[1]), "r"(a[2]), "r"(a[3]), "r"(b0), "r"(b1));
}
__device__ __forceinline__ void cpasync16(uint32_t dst, const void* src) {
    asm volatile("cp.async.cg.shared.global [%0], [%1], 16;"
                 :: "r"(dst), "l"(src) : "memory");
}

__global__ __launch_bounds__(256, 2)
void gemm_kv_mma(void)
{
    extern __shared__ char sm[];
    const uint32_t sb = smem_u32(sm);
    const int tid = threadIdx.x;
    const int wid = tid >> 5;
    const int lane = tid & 31;
    const int wm = wid >> 2;
    const int wn = wid & 3;

    const int m0 = blockIdx.y * TM;
    const int n0 = blockIdx.x * TN;

    const int crow = tid >> 1;
    const int q = tid & 1;
    const __half* srcA = g_Af16 + (size_t)(m0 + crow) * DD + q * 8;
    const __half* srcB = g_Bf16 + (size_t)(n0 + crow) * DD + q * 8;
    const uint32_t dbase = (uint32_t)(crow * PITCH + q * 16);

    float acc[4][4][4];
#pragma unroll
    for (int i = 0; i < 4; i++)
#pragma unroll
        for (int j = 0; j < 4; j++)
#pragma unroll
            for (int qq = 0; qq < 4; qq++) acc[i][j][qq] = 0.f;

    const uint32_t a_off =
        (uint32_t)((wm * 64 + (lane & 15)) * PITCH + ((lane & 16) ? 16 : 0));
    const uint32_t b_off =
        (uint32_t)((wn * 32 + (lane & 7) + ((lane & 16) ? 8 : 0)) * PITCH +
                   ((lane & 8) ? 16 : 0));

#define ISSUE_CHUNK(c)                                                          \
    do {                                                                        \
        const int k0_ = (c) * TK;                                               \
        const uint32_t st_ = sb + ((c) & (NSTG - 1)) * STAGE;                   \
        cpasync16(st_ + dbase,         srcA + k0_);                             \
        cpasync16(st_ + PLANE + dbase, srcB + k0_);                             \
        asm volatile("cp.async.commit_group;" ::: "memory");                    \
    } while (0)

    ISSUE_CHUNK(0);
    ISSUE_CHUNK(1);
    ISSUE_CHUNK(2);

    for (int c = 0; c < NCH; c++) {
        asm volatile("cp.async.wait_group 2;" ::: "memory");
        __syncthreads();
        const uint32_t st = sb + (c & (NSTG - 1)) * STAGE;

        uint32_t Af[4][4];
#pragma unroll
        for (int mt = 0; mt < 4; mt++)
            ldmx4(Af[mt], st + a_off + mt * 16 * PITCH);
#pragma unroll
        for (int np = 0; np < 2; np++) {
            uint32_t Bf[4];
            ldmx4(Bf, st + PLANE + b_off + np * 16 * PITCH);
#pragma unroll
            for (int mt = 0; mt < 4; mt++) {
                mma16816(acc[mt][2 * np],     Af[mt], Bf[0], Bf[1]);
                mma16816(acc[mt][2 * np + 1], Af[mt], Bf[2], Bf[3]);
            }
        }

        if (c + 3 < NCH) {
            ISSUE_CHUNK(c + 3);
        } else {
            asm volatile("cp.async.commit_group;" ::: "memory");
        }
    }

#pragma unroll
    for (int mt = 0; mt < 4; mt++) {
        const int row = m0 + wm * 64 + mt * 16 + (lane >> 2);
#pragma unroll
        for (int nt = 0; nt < 4; nt++) {
            const int col = n0 + wn * 32 + nt * 8 + 2 * (lane & 3);
            float* p0 = g_proj + (size_t)row * DD + col;
            float* p1 = g_proj + (size_t)(row + 8) * DD + col;
            *reinterpret_cast<float2*>(p0) = make_float2(acc[mt][nt][0], acc[mt][nt][1]);
            *reinterpret_cast<float2*>(p1) = make_float2(acc[mt][nt][2], acc[mt][nt][3]);
        }
    }
}

// ---------------------------------------------------------------------------
// Kernel 3: recurrence, 256 threads, 4-way DK split per state row.
// Thread = (v, quarter q); each owns 16 columns of W row v.
// gamma factored (W = S*U), renorm every 16 steps.
// ---------------------------------------------------------------------------
#define CH 32
#define KROW 80   // quarters at float offsets 0,20,40,60 (all 16B aligned)

__global__ __launch_bounds__(256)
void recurrent_update(const float* __restrict__ W_old,
                      const float* __restrict__ hd,
                      float* __restrict__ out)
{
    const int bh = blockIdx.x;
    const int b = bh >> 4;
    const int h = bh & 15;
    const int tid = threadIdx.x;
    const int v = tid >> 2;
    const int q = tid & 3;
    const int cb = q * 20;

    __shared__ float ks[CH][KROW];
    __shared__ float vs[CH][DKK];
    __shared__ float betas[TT], gams[TT], ginvs[TT];
    __shared__ float ninv[CH];

    float U[16];
    const float* wrow = W_old + ((size_t)bh * DKK + v) * DKK + q * 16;
#pragma unroll
    for (int d = 0; d < 16; d += 4) {
        float4 t = *reinterpret_cast<const float4*>(&wrow[d]);
        U[d] = t.x; U[d+1] = t.y; U[d+2] = t.z; U[d+3] = t.w;
    }
    const float hdl = hd[h];

    // precompute per-step scalars (256 threads, 1 step each)
    {
        int i = tid;
        size_t brow = (size_t)(b * TT + i) * 32;
        betas[i] = 1.f / (1.f + expf(-g_bg[brow + h]));
        float gm = 1.f / (1.f + expf(-(g_bg[brow + 16 + h] + hdl)));
        gams[i] = gm;
        ginvs[i] = 1.f / gm;
    }

    for (int t0 = 0; t0 < TT; t0 += CH) {
        __syncthreads();
        for (int i = tid; i < CH * DKK; i += 256) {
            int s = i >> 6, d = i & 63;
            int col = (d >> 4) * 20 + (d & 15);
            size_t row = (size_t)(b * TT + t0 + s) * DD;
            ks[s][col] = g_proj[row + h * DKK + d];
            vs[s][d] = g_proj[row + 1024 + h * DKK + d];
        }
        __syncthreads();
        // ninv: 8 lanes per step, 8 elems each
        {
            int s = tid >> 3, oc = tid & 7;
            int d0 = oc * 8;
            float nsq = 0.f;
#pragma unroll
            for (int dd = 0; dd < 8; dd++) {
                int d = d0 + dd;
                float x = ks[s][(d >> 4) * 20 + (d & 15)];
                nsq = fmaf(x, x, nsq);
            }
            nsq += __shfl_xor_sync(0xffffffffu, nsq, 1);
            nsq += __shfl_xor_sync(0xffffffffu, nsq, 2);
            nsq += __shfl_xor_sync(0xffffffffu, nsq, 4);
            if (oc == 0) ninv[s] = rsqrtf(fmaxf(nsq, 1e-24f));
        }
        __syncthreads();

#pragma unroll
        for (int hcb = 0; hcb < CH; hcb += 16) {
            float S = 1.f, invS = 1.f;
            for (int s = hcb; s < hcb + 16; s++) {
                const int t = t0 + s;
                S *= gams[t];
                invS *= ginvs[t];
                float kr[16];
#pragma unroll
                for (int d = 0; d < 16; d += 4) {
                    float4 tv = *reinterpret_cast<const float4*>(&ks[s][cb + d]);
                    kr[d] = tv.x; kr[d+1] = tv.y; kr[d+2] = tv.z; kr[d+3] = tv.w;
                }
                float a0 = 0.f, a1 = 0.f, a2 = 0.f, a3 = 0.f;
#pragma unroll
                for (int d = 0; d < 16; d += 4) {
                    a0 = fmaf(U[d],     kr[d],     a0);
                    a1 = fmaf(U[d + 1], kr[d + 1], a1);
                    a2 = fmaf(U[d + 2], kr[d + 2], a2);
                    a3 = fmaf(U[d + 3], kr[d + 3], a3);
                }
                float yr = (a0 + a1) + (a2 + a3);
                yr += __shfl_xor_sync(0xffffffffu, yr, 1);
                yr += __shfl_xor_sync(0xffffffffu, yr, 2);
                const float nv = ninv[s];
                float y = yr * nv;
                float yprev = S * ginvs[t] * y;
                float cc = betas[t] * (vs[s][v] - yprev) * invS * nv;
#pragma unroll
                for (int d = 0; d < 16; d++)
                    U[d] = fmaf(cc, kr[d], U[d]);
            }
#pragma unroll
            for (int d = 0; d < 16; d++)
                U[d] *= S;
        }
    }

    float* orow = out + ((size_t)bh * DKK + v) * DKK + q * 16;
#pragma unroll
    for (int d = 0; d < 16; d += 4) {
        float4 t = make_float4(U[d], U[d+1], U[d+2], U[d+3]);
        *reinterpret_cast<float4*>(&orow[d]) = t;
    }
}

// ---------------------------------------------------------------------------
extern "C" void kernel_launch(void* const* d_in, const int* in_sizes, int n_in,
                              void* d_out, int out_size)
{
    const float* W_old   = (const float*)d_in[0];
    const float* content = (const float*)d_in[1];
    const float* k_w     = (const float*)d_in[2];
    const float* v_w     = (const float*)d_in[3];
    const float* b_w     = (const float*)d_in[4];
    const float* b_b     = (const float*)d_in[5];
    const float* ts_w    = (const float*)d_in[6];
    const float* ts_b    = (const float*)d_in[7];
    const float* hd      = (const float*)d_in[8];
    float* out = (float*)d_out;

    proj_bg<<<256, 256>>>(content, b_w, ts_w, b_b, ts_b,
                          (const float4*)k_w, (const float4*)v_w);

    cudaFuncSetAttribute(gemm_kv_mma, cudaFuncAttributeMaxDynamicSharedMemorySize,
                         SMEMG);
    dim3 g1(DD / TN, 8192 / TM);   // (16, 64)
    gemm_kv_mma<<<g1, 256, SMEMG>>>();
    recurrent_update<<<BB * HH, 256>>>(W_old, hd, out);
}

// round 13
// speedup vs baseline: 1.0033x; 1.0033x over previous
#include <cuda_runtime.h>
#include <cuda_bf16.h>
#include <cuda_fp16.h>
#include <math.h>
#include <stdint.h>

// Problem constants
#define BB 32
#define TT 256
#define DD 2048
#define HH 16
#define DKK 64

__device__ float g_proj[8192 * 2048];   // k|v projections (B*T, 2048)
__device__ float g_bg[8192 * 32];       // beta logits (0..15), gamma logits (16..31)

// fp16 operand planes (single product: C = A_f16 * B_f16)
__device__ __half g_Af16[8192 * 2048];  // content (written by proj_bg)
__device__ __half g_Bf16[2048 * 2048];  // weights; rows 0..1023 = k_w, 1024.. = v_w

__device__ __forceinline__ uint32_t smem_u32(const void* p) {
    uint32_t a;
    asm("{ .reg .u64 t; cvta.to.shared.u64 t, %1; cvt.u32.u64 %0, t; }" : "=r"(a) : "l"(p));
    return a;
}

// ---------------------------------------------------------------------------
// Kernel 0: convert weights to fp16 plane
// ---------------------------------------------------------------------------
#define N4_W (1024 * 2048 / 4)

__global__ __launch_bounds__(256)
void cvt_w(const float4* __restrict__ kw, const float4* __restrict__ vw)
{
    int i = blockIdx.x * blockDim.x + threadIdx.x;
    const int total = 2 * N4_W;
    const int stride = gridDim.x * blockDim.x;
    for (; i < total; i += stride) {
        const float4* src = (i < N4_W) ? kw : vw;
        uint2* dst = (i < N4_W) ? (uint2*)g_Bf16 : (uint2*)(g_Bf16 + 1024 * 2048);
        int j = (i < N4_W) ? i : i - N4_W;
        float4 x = src[j];
        uint2 hv;
        asm("cvt.rn.f16x2.f32 %0, %2, %1;" : "=r"(hv.x) : "f"(x.x), "f"(x.y));
        asm("cvt.rn.f16x2.f32 %0, %2, %1;" : "=r"(hv.y) : "f"(x.z), "f"(x.w));
        dst[j] = hv;
    }
}

// ---------------------------------------------------------------------------
// Kernel 2: beta/gamma logits + content->fp16 fused.
// 512 blocks x 128 threads, 16 rows/block, K-chunk 64, 2x2 blocking.
// ---------------------------------------------------------------------------
__global__ __launch_bounds__(128)
void proj_bg(const float* __restrict__ A,
             const float* __restrict__ b_w,
             const float* __restrict__ ts_w,
             const float* __restrict__ b_b,
             const float* __restrict__ ts_b)
{
    __shared__ float As[16][64];
    __shared__ float Ws[32][65];

    const int rb = blockIdx.x * 16;
    const int tid = threadIdx.x;
    const int r0 = (tid >> 4) * 2;      // 0..14
    const int j0 = (tid & 15) * 2;      // 0..30
    float a00 = 0.f, a01 = 0.f, a10 = 0.f, a11 = 0.f;

    for (int k0 = 0; k0 < DD; k0 += 64) {
        __syncthreads();
        // stage A (16 rows x 64) + emit fp16
#pragma unroll
        for (int it = 0; it < 4; it++) {
            int idx = tid + it * 128;          // 0..511 float2
            int row = idx >> 5, c2 = idx & 31;
            const float2 v = *reinterpret_cast<const float2*>(
                A + (size_t)(rb + row) * DD + k0 + c2 * 2);
            As[row][c2 * 2] = v.x;
            As[row][c2 * 2 + 1] = v.y;
            uint32_t hcv;
            asm("cvt.rn.f16x2.f32 %0, %2, %1;" : "=r"(hcv) : "f"(v.x), "f"(v.y));
            *reinterpret_cast<uint32_t*>(
                g_Af16 + (size_t)(rb + row) * DD + k0 + c2 * 2) = hcv;
        }
        // stage W (32 rows x 64)
#pragma unroll
        for (int it = 0; it < 8; it++) {
            int idx = tid + it * 128;          // 0..1023 float2
            int wr = idx >> 5, wc2 = idx & 31;
            const float* wsrc = (wr < 16) ? (b_w + (size_t)wr * DD)
                                          : (ts_w + (size_t)(wr - 16) * DD);
            const float2 v = *reinterpret_cast<const float2*>(wsrc + k0 + wc2 * 2);
            Ws[wr][wc2 * 2] = v.x;
            Ws[wr][wc2 * 2 + 1] = v.y;
        }
        __syncthreads();
#pragma unroll 4
        for (int d = 0; d < 64; d++) {
            float x0 = As[r0][d], x1 = As[r0 + 1][d];
            float w0 = Ws[j0][d], w1 = Ws[j0 + 1][d];
            a00 = fmaf(x0, w0, a00);
            a01 = fmaf(x0, w1, a01);
            a10 = fmaf(x1, w0, a10);
            a11 = fmaf(x1, w1, a11);
        }
    }

    float bias0 = (j0 < 16) ? b_b[j0] : ts_b[j0 - 16];
    float bias1 = (j0 + 1 < 16) ? b_b[j0 + 1] : ts_b[j0 + 1 - 16];
    g_bg[(size_t)(rb + r0) * 32 + j0]         = a00 + bias0;
    g_bg[(size_t)(rb + r0) * 32 + j0 + 1]     = a01 + bias1;
    g_bg[(size_t)(rb + r0 + 1) * 32 + j0]     = a10 + bias0;
    g_bg[(size_t)(rb + r0 + 1) * 32 + j0 + 1] = a11 + bias1;
}

// ---------------------------------------------------------------------------
// Kernel 1: GEMM, single-product fp16.
// CTA 128x128, K-chunk 16, 4-stage cp.async pipeline, warp layout 2x4.
// ---------------------------------------------------------------------------
#define TM 128
#define TN 128
#define TK 16
#define NCH (DD / TK)        // 128
#define PITCH 48
#define PLANE (128 * PITCH)  // 6144
#define STAGE (2 * PLANE)    // 12288
#define NSTG 4
#define SMEMG (NSTG * STAGE) // 49152

__device__ __forceinline__ void ldmx4(uint32_t* r, uint32_t addr) {
    asm volatile("ldmatrix.sync.aligned.m8n8.x4.shared.b16 {%0,%1,%2,%3}, [%4];"
                 : "=r"(r[0]), "=r"(r[1]), "=r"(r[2]), "=r"(r[3]) : "r"(addr));
}
__device__ __forceinline__ void mma16816(float* d, const uint32_t* a,
                                         uint32_t b0, uint32_t b1) {
    asm volatile(
        "mma.sync.aligned.m16n8k16.row.col.f32.f16.f16.f32 "
        "{%0,%1,%2,%3}, {%4,%5,%6,%7}, {%8,%9}, {%0,%1,%2,%3};"
        : "+f"(d[0]), "+f"(d[1]), "+f"(d[2]), "+f"(d[3])
        : "r"(a[0]), "r"(a[1]), "r"(a[2]), "r"(a[3]), "r"(b0), "r"(b1));
}
__device__ __forceinline__ void cpasync16(uint32_t dst, const void* src) {
    asm volatile("cp.async.cg.shared.global [%0], [%1], 16;"
                 :: "r"(dst), "l"(src) : "memory");
}

__global__ __launch_bounds__(256, 2)
void gemm_kv_mma(void)
{
    extern __shared__ char sm[];
    const uint32_t sb = smem_u32(sm);
    const int tid = threadIdx.x;
    const int wid = tid >> 5;
    const int lane = tid & 31;
    const int wm = wid >> 2;
    const int wn = wid & 3;

    const int m0 = blockIdx.y * TM;
    const int n0 = blockIdx.x * TN;

    const int crow = tid >> 1;
    const int q = tid & 1;
    const __half* srcA = g_Af16 + (size_t)(m0 + crow) * DD + q * 8;
    const __half* srcB = g_Bf16 + (size_t)(n0 + crow) * DD + q * 8;
    const uint32_t dbase = (uint32_t)(crow * PITCH + q * 16);

    float acc[4][4][4];
#pragma unroll
    for (int i = 0; i < 4; i++)
#pragma unroll
        for (int j = 0; j < 4; j++)
#pragma unroll
            for (int qq = 0; qq < 4; qq++) acc[i][j][qq] = 0.f;

    const uint32_t a_off =
        (uint32_t)((wm * 64 + (lane & 15)) * PITCH + ((lane & 16) ? 16 : 0));
    const uint32_t b_off =
        (uint32_t)((wn * 32 + (lane & 7) + ((lane & 16) ? 8 : 0)) * PITCH +
                   ((lane & 8) ? 16 : 0));

#define ISSUE_CHUNK(c)                                                          \
    do {                                                                        \
        const int k0_ = (c) * TK;                                               \
        const uint32_t st_ = sb + ((c) & (NSTG - 1)) * STAGE;                   \
        cpasync16(st_ + dbase,         srcA + k0_);                             \
        cpasync16(st_ + PLANE + dbase, srcB + k0_);                             \
        asm volatile("cp.async.commit_group;" ::: "memory");                    \
    } while (0)

    ISSUE_CHUNK(0);
    ISSUE_CHUNK(1);
    ISSUE_CHUNK(2);

    for (int c = 0; c < NCH; c++) {
        asm volatile("cp.async.wait_group 2;" ::: "memory");
        __syncthreads();
        const uint32_t st = sb + (c & (NSTG - 1)) * STAGE;

        uint32_t Af[4][4];
#pragma unroll
        for (int mt = 0; mt < 4; mt++)
            ldmx4(Af[mt], st + a_off + mt * 16 * PITCH);
#pragma unroll
        for (int np = 0; np < 2; np++) {
            uint32_t Bf[4];
            ldmx4(Bf, st + PLANE + b_off + np * 16 * PITCH);
#pragma unroll
            for (int mt = 0; mt < 4; mt++) {
                mma16816(acc[mt][2 * np],     Af[mt], Bf[0], Bf[1]);
                mma16816(acc[mt][2 * np + 1], Af[mt], Bf[2], Bf[3]);
            }
        }

        if (c + 3 < NCH) {
            ISSUE_CHUNK(c + 3);
        } else {
            asm volatile("cp.async.commit_group;" ::: "memory");
        }
    }

#pragma unroll
    for (int mt = 0; mt < 4; mt++) {
        const int row = m0 + wm * 64 + mt * 16 + (lane >> 2);
#pragma unroll
        for (int nt = 0; nt < 4; nt++) {
            const int col = n0 + wn * 32 + nt * 8 + 2 * (lane & 3);
            float* p0 = g_proj + (size_t)row * DD + col;
            float* p1 = g_proj + (size_t)(row + 8) * DD + col;
            *reinterpret_cast<float2*>(p0) = make_float2(acc[mt][nt][0], acc[mt][nt][1]);
            *reinterpret_cast<float2*>(p1) = make_float2(acc[mt][nt][2], acc[mt][nt][3]);
        }
    }
}

// ---------------------------------------------------------------------------
// Kernel 3: recurrence, 256 threads, 4-way DK split per state row.
// gamma factored (W = S*U), renorm every 16 steps.
// ---------------------------------------------------------------------------
#define CH 32
#define KROW 80   // quarters at float offsets 0,20,40,60 (all 16B aligned)

__global__ __launch_bounds__(256)
void recurrent_update(const float* __restrict__ W_old,
                      const float* __restrict__ hd,
                      float* __restrict__ out)
{
    const int bh = blockIdx.x;
    const int b = bh >> 4;
    const int h = bh & 15;
    const int tid = threadIdx.x;
    const int v = tid >> 2;
    const int q = tid & 3;
    const int cb = q * 20;

    __shared__ float ks[CH][KROW];
    __shared__ float vs[CH][DKK];
    __shared__ float betas[TT], gams[TT], ginvs[TT];
    __shared__ float ninv[CH];

    float U[16];
    const float* wrow = W_old + ((size_t)bh * DKK + v) * DKK + q * 16;
#pragma unroll
    for (int d = 0; d < 16; d += 4) {
        float4 t = *reinterpret_cast<const float4*>(&wrow[d]);
        U[d] = t.x; U[d+1] = t.y; U[d+2] = t.z; U[d+3] = t.w;
    }
    const float hdl = hd[h];

    {
        int i = tid;
        size_t brow = (size_t)(b * TT + i) * 32;
        betas[i] = 1.f / (1.f + expf(-g_bg[brow + h]));
        float gm = 1.f / (1.f + expf(-(g_bg[brow + 16 + h] + hdl)));
        gams[i] = gm;
        ginvs[i] = 1.f / gm;
    }

    for (int t0 = 0; t0 < TT; t0 += CH) {
        __syncthreads();
        for (int i = tid; i < CH * DKK; i += 256) {
            int s = i >> 6, d = i & 63;
            int col = (d >> 4) * 20 + (d & 15);
            size_t row = (size_t)(b * TT + t0 + s) * DD;
            ks[s][col] = g_proj[row + h * DKK + d];
            vs[s][d] = g_proj[row + 1024 + h * DKK + d];
        }
        __syncthreads();
        {
            int s = tid >> 3, oc = tid & 7;
            int d0 = oc * 8;
            float nsq = 0.f;
#pragma unroll
            for (int dd = 0; dd < 8; dd++) {
                int d = d0 + dd;
                float x = ks[s][(d >> 4) * 20 + (d & 15)];
                nsq = fmaf(x, x, nsq);
            }
            nsq += __shfl_xor_sync(0xffffffffu, nsq, 1);
            nsq += __shfl_xor_sync(0xffffffffu, nsq, 2);
            nsq += __shfl_xor_sync(0xffffffffu, nsq, 4);
            if (oc == 0) ninv[s] = rsqrtf(fmaxf(nsq, 1e-24f));
        }
        __syncthreads();

#pragma unroll
        for (int hcb = 0; hcb < CH; hcb += 16) {
            float S = 1.f, invS = 1.f;
            for (int s = hcb; s < hcb + 16; s++) {
                const int t = t0 + s;
                S *= gams[t];
                invS *= ginvs[t];
                float kr[16];
#pragma unroll
                for (int d = 0; d < 16; d += 4) {
                    float4 tv = *reinterpret_cast<const float4*>(&ks[s][cb + d]);
                    kr[d] = tv.x; kr[d+1] = tv.y; kr[d+2] = tv.z; kr[d+3] = tv.w;
                }
                float a0 = 0.f, a1 = 0.f, a2 = 0.f, a3 = 0.f;
#pragma unroll
                for (int d = 0; d < 16; d += 4) {
                    a0 = fmaf(U[d],     kr[d],     a0);
                    a1 = fmaf(U[d + 1], kr[d + 1], a1);
                    a2 = fmaf(U[d + 2], kr[d + 2], a2);
                    a3 = fmaf(U[d + 3], kr[d + 3], a3);
                }
                float yr = (a0 + a1) + (a2 + a3);
                yr += __shfl_xor_sync(0xffffffffu, yr, 1);
                yr += __shfl_xor_sync(0xffffffffu, yr, 2);
                const float nv = ninv[s];
                float y = yr * nv;
                float yprev = S * ginvs[t] * y;
                float cc = betas[t] * (vs[s][v] - yprev) * invS * nv;
#pragma unroll
                for (int d = 0; d < 16; d++)
                    U[d] = fmaf(cc, kr[d], U[d]);
            }
#pragma unroll
            for (int d = 0; d < 16; d++)
                U[d] *= S;
        }
    }

    float* orow = out + ((size_t)bh * DKK + v) * DKK + q * 16;
#pragma unroll
    for (int d = 0; d < 16; d += 4) {
        float4 t = make_float4(U[d], U[d+1], U[d+2], U[d+3]);
        *reinterpret_cast<float4*>(&orow[d]) = t;
    }
}

// ---------------------------------------------------------------------------
extern "C" void kernel_launch(void* const* d_in, const int* in_sizes, int n_in,
                              void* d_out, int out_size)
{
    const float* W_old   = (const float*)d_in[0];
    const float* content = (const float*)d_in[1];
    const float* k_w     = (const float*)d_in[2];
    const float* v_w     = (const float*)d_in[3];
    const float* b_w     = (const float*)d_in[4];
    const float* b_b     = (const float*)d_in[5];
    const float* ts_w    = (const float*)d_in[6];
    const float* ts_b    = (const float*)d_in[7];
    const float* hd      = (const float*)d_in[8];
    float* out = (float*)d_out;

    cvt_w<<<1024, 256>>>((const float4*)k_w, (const float4*)v_w);
    proj_bg<<<512, 128>>>(content, b_w, ts_w, b_b, ts_b);   // also emits g_Af16

    cudaFuncSetAttribute(gemm_kv_mma, cudaFuncAttributeMaxDynamicSharedMemorySize,
                         SMEMG);
    dim3 g1(DD / TN, 8192 / TM);   // (16, 64)
    gemm_kv_mma<<<g1, 256, SMEMG>>>();
    recurrent_update<<<BB * HH, 256>>>(W_old, hd, out);
}

// round 14
// speedup vs baseline: 1.0447x; 1.0413x over previous
#include <cuda_runtime.h>
#include <cuda_bf16.h>
#include <cuda_fp16.h>
#include <math.h>
#include <stdint.h>

// Problem constants
#define BB 32
#define TT 256
#define DD 2048
#define HH 16
#define DKK 64

__device__ float g_proj[8192 * 2048];   // k|v projections (B*T, 2048)
__device__ float g_bg[8192 * 32];       // beta logits (0..15), gamma logits (16..31)

// fp16 operand planes (single product: C = A_f16 * B_f16)
__device__ __half g_Af16[8192 * 2048];  // content (written by proj_bg)
__device__ __half g_Bf16[2048 * 2048];  // weights; rows 0..1023 = k_w, 1024.. = v_w

__device__ __forceinline__ uint32_t smem_u32(const void* p) {
    uint32_t a;
    asm("{ .reg .u64 t; cvta.to.shared.u64 t, %1; cvt.u32.u64 %0, t; }" : "=r"(a) : "l"(p));
    return a;
}

// ---------------------------------------------------------------------------
// Kernel 0: convert weights to fp16 plane
// ---------------------------------------------------------------------------
#define N4_W (1024 * 2048 / 4)

__global__ __launch_bounds__(256)
void cvt_w(const float4* __restrict__ kw, const float4* __restrict__ vw)
{
    int i = blockIdx.x * blockDim.x + threadIdx.x;
    const int total = 2 * N4_W;
    const int stride = gridDim.x * blockDim.x;
    for (; i < total; i += stride) {
        const float4* src = (i < N4_W) ? kw : vw;
        uint2* dst = (i < N4_W) ? (uint2*)g_Bf16 : (uint2*)(g_Bf16 + 1024 * 2048);
        int j = (i < N4_W) ? i : i - N4_W;
        float4 x = src[j];
        uint2 hv;
        asm("cvt.rn.f16x2.f32 %0, %2, %1;" : "=r"(hv.x) : "f"(x.x), "f"(x.y));
        asm("cvt.rn.f16x2.f32 %0, %2, %1;" : "=r"(hv.y) : "f"(x.z), "f"(x.w));
        dst[j] = hv;
    }
}

// ---------------------------------------------------------------------------
// Kernel 2: beta/gamma logits + content->fp16 fused.
// 512 blocks x 128 threads, 16 rows/block, K-chunk 64, 2x2 blocking.
// ---------------------------------------------------------------------------
__global__ __launch_bounds__(128)
void proj_bg(const float* __restrict__ A,
             const float* __restrict__ b_w,
             const float* __restrict__ ts_w,
             const float* __restrict__ b_b,
             const float* __restrict__ ts_b)
{
    __shared__ float As[16][64];
    __shared__ float Ws[32][65];

    const int rb = blockIdx.x * 16;
    const int tid = threadIdx.x;
    const int r0 = (tid >> 4) * 2;      // 0..14
    const int j0 = (tid & 15) * 2;      // 0..30
    float a00 = 0.f, a01 = 0.f, a10 = 0.f, a11 = 0.f;

    for (int k0 = 0; k0 < DD; k0 += 64) {
        __syncthreads();
#pragma unroll
        for (int it = 0; it < 4; it++) {
            int idx = tid + it * 128;          // 0..511 float2
            int row = idx >> 5, c2 = idx & 31;
            const float2 v = *reinterpret_cast<const float2*>(
                A + (size_t)(rb + row) * DD + k0 + c2 * 2);
            As[row][c2 * 2] = v.x;
            As[row][c2 * 2 + 1] = v.y;
            uint32_t hcv;
            asm("cvt.rn.f16x2.f32 %0, %2, %1;" : "=r"(hcv) : "f"(v.x), "f"(v.y));
            *reinterpret_cast<uint32_t*>(
                g_Af16 + (size_t)(rb + row) * DD + k0 + c2 * 2) = hcv;
        }
#pragma unroll
        for (int it = 0; it < 8; it++) {
            int idx = tid + it * 128;          // 0..1023 float2
            int wr = idx >> 5, wc2 = idx & 31;
            const float* wsrc = (wr < 16) ? (b_w + (size_t)wr * DD)
                                          : (ts_w + (size_t)(wr - 16) * DD);
            const float2 v = *reinterpret_cast<const float2*>(wsrc + k0 + wc2 * 2);
            Ws[wr][wc2 * 2] = v.x;
            Ws[wr][wc2 * 2 + 1] = v.y;
        }
        __syncthreads();
#pragma unroll 4
        for (int d = 0; d < 64; d++) {
            float x0 = As[r0][d], x1 = As[r0 + 1][d];
            float w0 = Ws[j0][d], w1 = Ws[j0 + 1][d];
            a00 = fmaf(x0, w0, a00);
            a01 = fmaf(x0, w1, a01);
            a10 = fmaf(x1, w0, a10);
            a11 = fmaf(x1, w1, a11);
        }
    }

    float bias0 = (j0 < 16) ? b_b[j0] : ts_b[j0 - 16];
    float bias1 = (j0 + 1 < 16) ? b_b[j0 + 1] : ts_b[j0 + 1 - 16];
    g_bg[(size_t)(rb + r0) * 32 + j0]         = a00 + bias0;
    g_bg[(size_t)(rb + r0) * 32 + j0 + 1]     = a01 + bias1;
    g_bg[(size_t)(rb + r0 + 1) * 32 + j0]     = a10 + bias0;
    g_bg[(size_t)(rb + r0 + 1) * 32 + j0 + 1] = a11 + bias1;
}

// ---------------------------------------------------------------------------
// Kernel 1: GEMM, single-product fp16.
// CTA 128x128, K-chunk 16, 4-stage cp.async pipeline, warp layout 2x4.
// ---------------------------------------------------------------------------
#define TM 128
#define TN 128
#define TK 16
#define NCH (DD / TK)        // 128
#define PITCH 48
#define PLANE (128 * PITCH)  // 6144
#define STAGE (2 * PLANE)    // 12288
#define NSTG 4
#define SMEMG (NSTG * STAGE) // 49152

__device__ __forceinline__ void ldmx4(uint32_t* r, uint32_t addr) {
    asm volatile("ldmatrix.sync.aligned.m8n8.x4.shared.b16 {%0,%1,%2,%3}, [%4];"
                 : "=r"(r[0]), "=r"(r[1]), "=r"(r[2]), "=r"(r[3]) : "r"(addr));
}
__device__ __forceinline__ void mma16816(float* d, const uint32_t* a,
                                         uint32_t b0, uint32_t b1) {
    asm volatile(
        "mma.sync.aligned.m16n8k16.row.col.f32.f16.f16.f32 "
        "{%0,%1,%2,%3}, {%4,%5,%6,%7}, {%8,%9}, {%0,%1,%2,%3};"
        : "+f"(d[0]), "+f"(d[1]), "+f"(d[2]), "+f"(d[3])
        : "r"(a[0]), "r"(a[1]), "r"(a[2]), "r"(a[3]), "r"(b0), "r"(b1));
}
__device__ __forceinline__ void cpasync16(uint32_t dst, const void* src) {
    asm volatile("cp.async.cg.shared.global [%0], [%1], 16;"
                 :: "r"(dst), "l"(src) : "memory");
}

__global__ __launch_bounds__(256, 2)
void gemm_kv_mma(void)
{
    extern __shared__ char sm[];
    const uint32_t sb = smem_u32(sm);
    const int tid = threadIdx.x;
    const int wid = tid >> 5;
    const int lane = tid & 31;
    const int wm = wid >> 2;
    const int wn = wid & 3;

    const int m0 = blockIdx.y * TM;
    const int n0 = blockIdx.x * TN;

    const int crow = tid >> 1;
    const int q = tid & 1;
    const __half* srcA = g_Af16 + (size_t)(m0 + crow) * DD + q * 8;
    const __half* srcB = g_Bf16 + (size_t)(n0 + crow) * DD + q * 8;
    const uint32_t dbase = (uint32_t)(crow * PITCH + q * 16);

    float acc[4][4][4];
#pragma unroll
    for (int i = 0; i < 4; i++)
#pragma unroll
        for (int j = 0; j < 4; j++)
#pragma unroll
            for (int qq = 0; qq < 4; qq++) acc[i][j][qq] = 0.f;

    const uint32_t a_off =
        (uint32_t)((wm * 64 + (lane & 15)) * PITCH + ((lane & 16) ? 16 : 0));
    const uint32_t b_off =
        (uint32_t)((wn * 32 + (lane & 7) + ((lane & 16) ? 8 : 0)) * PITCH +
                   ((lane & 8) ? 16 : 0));

#define ISSUE_CHUNK(c)                                                          \
    do {                                                                        \
        const int k0_ = (c) * TK;                                               \
        const uint32_t st_ = sb + ((c) & (NSTG - 1)) * STAGE;                   \
        cpasync16(st_ + dbase,         srcA + k0_);                             \
        cpasync16(st_ + PLANE + dbase, srcB + k0_);                             \
        asm volatile("cp.async.commit_group;" ::: "memory");                    \
    } while (0)

    ISSUE_CHUNK(0);
    ISSUE_CHUNK(1);
    ISSUE_CHUNK(2);

    for (int c = 0; c < NCH; c++) {
        asm volatile("cp.async.wait_group 2;" ::: "memory");
        __syncthreads();
        const uint32_t st = sb + (c & (NSTG - 1)) * STAGE;

        uint32_t Af[4][4];
#pragma unroll
        for (int mt = 0; mt < 4; mt++)
            ldmx4(Af[mt], st + a_off + mt * 16 * PITCH);
#pragma unroll
        for (int np = 0; np < 2; np++) {
            uint32_t Bf[4];
            ldmx4(Bf, st + PLANE + b_off + np * 16 * PITCH);
#pragma unroll
            for (int mt = 0; mt < 4; mt++) {
                mma16816(acc[mt][2 * np],     Af[mt], Bf[0], Bf[1]);
                mma16816(acc[mt][2 * np + 1], Af[mt], Bf[2], Bf[3]);
            }
        }

        if (c + 3 < NCH) {
            ISSUE_CHUNK(c + 3);
        } else {
            asm volatile("cp.async.commit_group;" ::: "memory");
        }
    }

#pragma unroll
    for (int mt = 0; mt < 4; mt++) {
        const int row = m0 + wm * 64 + mt * 16 + (lane >> 2);
#pragma unroll
        for (int nt = 0; nt < 4; nt++) {
            const int col = n0 + wn * 32 + nt * 8 + 2 * (lane & 3);
            float* p0 = g_proj + (size_t)row * DD + col;
            float* p1 = g_proj + (size_t)(row + 8) * DD + col;
            *reinterpret_cast<float2*>(p0) = make_float2(acc[mt][nt][0], acc[mt][nt][1]);
            *reinterpret_cast<float2*>(p1) = make_float2(acc[mt][nt][2], acc[mt][nt][3]);
        }
    }
}

// ---------------------------------------------------------------------------
// Kernel 3: recurrence (round-11 version): 128 threads, lane pairs split DK.
// gamma factored (W = S*U), renorm every 16 steps; precomputed scalars.
// ---------------------------------------------------------------------------
#define CH 32
#define KROW 72

__global__ __launch_bounds__(128)
void recurrent_update(const float* __restrict__ W_old,
                      const float* __restrict__ hd,
                      float* __restrict__ out)
{
    const int bh = blockIdx.x;
    const int b = bh >> 4;
    const int h = bh & 15;
    const int tid = threadIdx.x;
    const int v = tid >> 1;
    const int half = tid & 1;
    const int cb = half ? 36 : 0;

    __shared__ float ks[CH][KROW];
    __shared__ float vs[CH][DKK];
    __shared__ float betas[TT], gams[TT], ginvs[TT];
    __shared__ float ninv[CH];

    float U[32];
    const float* wrow = W_old + ((size_t)bh * DKK + v) * DKK + half * 32;
#pragma unroll
    for (int d = 0; d < 32; d += 4) {
        float4 t = *reinterpret_cast<const float4*>(&wrow[d]);
        U[d] = t.x; U[d+1] = t.y; U[d+2] = t.z; U[d+3] = t.w;
    }
    const float hdl = hd[h];

    // precompute per-step scalars with all 128 threads (2 steps each)
    for (int i = tid; i < TT; i += 128) {
        size_t brow = (size_t)(b * TT + i) * 32;
        betas[i] = 1.f / (1.f + expf(-g_bg[brow + h]));
        float gm = 1.f / (1.f + expf(-(g_bg[brow + 16 + h] + hdl)));
        gams[i] = gm;
        ginvs[i] = 1.f / gm;
    }

    for (int t0 = 0; t0 < TT; t0 += CH) {
        __syncthreads();
        for (int i = tid; i < CH * DKK; i += 128) {
            int s = i >> 6, d = i & 63;
            int col = d + ((d >= 32) ? 4 : 0);
            size_t row = (size_t)(b * TT + t0 + s) * DD;
            ks[s][col] = g_proj[row + h * DKK + d];
            vs[s][d] = g_proj[row + 1024 + h * DKK + d];
        }
        __syncthreads();
        // ninv: 4 lanes per step, 16 elems each, shfl-quad reduce
        {
            int s = tid >> 2, qq = tid & 3;
            int base = qq * 16 + ((qq >= 2) ? 4 : 0);
            float nsq = 0.f;
#pragma unroll
            for (int d = 0; d < 16; d++) {
                float x = ks[s][base + d];
                nsq = fmaf(x, x, nsq);
            }
            nsq += __shfl_xor_sync(0xffffffffu, nsq, 1);
            nsq += __shfl_xor_sync(0xffffffffu, nsq, 2);
            if (qq == 0) ninv[s] = rsqrtf(fmaxf(nsq, 1e-24f));
        }
        __syncthreads();

#pragma unroll
        for (int hcb = 0; hcb < CH; hcb += 16) {
            float S = 1.f, invS = 1.f;
            for (int s = hcb; s < hcb + 16; s++) {
                const int t = t0 + s;
                S *= gams[t];
                invS *= ginvs[t];
                float kr[32];
#pragma unroll
                for (int d = 0; d < 32; d += 4) {
                    float4 tv = *reinterpret_cast<const float4*>(&ks[s][cb + d]);
                    kr[d] = tv.x; kr[d+1] = tv.y; kr[d+2] = tv.z; kr[d+3] = tv.w;
                }
                float a0 = 0.f, a1 = 0.f, a2 = 0.f, a3 = 0.f;
#pragma unroll
                for (int d = 0; d < 32; d += 4) {
                    a0 = fmaf(U[d],     kr[d],     a0);
                    a1 = fmaf(U[d + 1], kr[d + 1], a1);
                    a2 = fmaf(U[d + 2], kr[d + 2], a2);
                    a3 = fmaf(U[d + 3], kr[d + 3], a3);
                }
                float yr = (a0 + a1) + (a2 + a3);
                yr += __shfl_xor_sync(0xffffffffu, yr, 1);
                const float nv = ninv[s];
                float y = yr * nv;
                float yprev = S * ginvs[t] * y;
                float cc = betas[t] * (vs[s][v] - yprev) * invS * nv;
#pragma unroll
                for (int d = 0; d < 32; d++)
                    U[d] = fmaf(cc, kr[d], U[d]);
            }
#pragma unroll
            for (int d = 0; d < 32; d++)
                U[d] *= S;
        }
    }

    float* orow = out + ((size_t)bh * DKK + v) * DKK + half * 32;
#pragma unroll
    for (int d = 0; d < 32; d += 4) {
        float4 t = make_float4(U[d], U[d+1], U[d+2], U[d+3]);
        *reinterpret_cast<float4*>(&orow[d]) = t;
    }
}

// ---------------------------------------------------------------------------
extern "C" void kernel_launch(void* const* d_in, const int* in_sizes, int n_in,
                              void* d_out, int out_size)
{
    const float* W_old   = (const float*)d_in[0];
    const float* content = (const float*)d_in[1];
    const float* k_w     = (const float*)d_in[2];
    const float* v_w     = (const float*)d_in[3];
    const float* b_w     = (const float*)d_in[4];
    const float* b_b     = (const float*)d_in[5];
    const float* ts_w    = (const float*)d_in[6];
    const float* ts_b    = (const float*)d_in[7];
    const float* hd      = (const float*)d_in[8];
    float* out = (float*)d_out;

    cvt_w<<<1024, 256>>>((const float4*)k_w, (const float4*)v_w);
    proj_bg<<<512, 128>>>(content, b_w, ts_w, b_b, ts_b);   // also emits g_Af16

    cudaFuncSetAttribute(gemm_kv_mma, cudaFuncAttributeMaxDynamicSharedMemorySize,
                         SMEMG);
    dim3 g1(DD / TN, 8192 / TM);   // (16, 64)
    gemm_kv_mma<<<g1, 256, SMEMG>>>();
    recurrent_update<<<BB * HH, 128>>>(W_old, hd, out);
}